// round 5
// baseline (speedup 1.0000x reference)
#include <cuda_runtime.h>

#define B_  4
#define S_  2048
#define D_  1024
#define H_  16
#define DK_ 64
#define SCALE_ 0.125f          // 1/sqrt(64)
#define LN_EPS_ 1e-5f

#define BSD ((size_t)B_ * S_ * D_)            // 8,388,608
#define NMASK ((size_t)B_ * S_ * S_)          // 16,777,216
#define NATTN ((size_t)B_ * H_ * S_ * S_)     // 268,435,456

// ---------------- device scratch (module-load allocated, no runtime alloc) ----
__device__ float g_Q[BSD];
__device__ float g_K[BSD];
__device__ float g_V[BSD];
__device__ float g_ctx[BSD];
__device__ float g_out[BSD];
__device__ float g_inv[(size_t)B_ * H_ * S_];   // 1/rowsum, row = (h*B+b)*S+q
__device__ unsigned char g_mask[NMASK];
__device__ int g_mask_mode;

// ---------------- mask dtype detection -------------------------------------
__global__ void detect_mask_kernel(const unsigned int* __restrict__ w) {
    __shared__ unsigned int sh;
    if (threadIdx.x == 0) sh = 0u;
    __syncthreads();
    unsigned int acc = 0u;
    for (int i = threadIdx.x; i < 65536; i += 256) acc |= w[i];
    atomicOr(&sh, acc);
    __syncthreads();
    if (threadIdx.x == 0) {
        unsigned int o = sh;
        int mode;
        if (o & 0x0000FF00u)              mode = 0; // uint8 bools (byte1 used)
        else if ((o & 0xFFFFFF00u) == 0u) mode = 1; // int32 0/1
        else                              mode = 2; // float32 0.0/1.0
        g_mask_mode = mode;
    }
}

__global__ void convert_mask_kernel(const void* __restrict__ mptr) {
    const int mode = g_mask_mode;
    const size_t n = NMASK;
    const size_t stride = (size_t)gridDim.x * blockDim.x;
    for (size_t i = (size_t)blockIdx.x * blockDim.x + threadIdx.x; i < n; i += stride) {
        unsigned char v;
        if (mode == 0)      v = ((const unsigned char*)mptr)[i];
        else if (mode == 1) v = (unsigned char)(((const int*)mptr)[i] != 0);
        else                v = (unsigned char)(((const float*)mptr)[i] != 0.0f);
        g_mask[i] = v;
    }
}

// ---------------- generic NT GEMM: C = A @ Bw^T + bias (+ resid) ------------
// A: [M,K] row-major, Bw: [N,K] row-major. Tile 64x64, K-chunk 16, 256 thr, 4x4 micro.
__global__ __launch_bounds__(256) void gemm_nt_kernel(
    const float* __restrict__ A, const float* __restrict__ Bw,
    const float* __restrict__ bias, const float* __restrict__ resid,
    float* __restrict__ C, int M, int N, int K)
{
    __shared__ float As[16 * 64];   // As[kk][m]
    __shared__ float Bs[16 * 64];   // Bs[kk][n]
    const int t  = threadIdx.x;
    const int tx = t & 15, ty = t >> 4;
    const int bm = blockIdx.y * 64, bn = blockIdx.x * 64;
    const int lr = t >> 2, lc = (t & 3) << 2;

    const float* Ap = A  + (size_t)(bm + lr) * K + lc;
    const float* Bp = Bw + (size_t)(bn + lr) * K + lc;

    float acc[4][4] = {};
    for (int k0 = 0; k0 < K; k0 += 16) {
        float4 av = *(const float4*)(Ap + k0);
        float4 bv = *(const float4*)(Bp + k0);
        __syncthreads();
        As[(lc + 0) * 64 + lr] = av.x; As[(lc + 1) * 64 + lr] = av.y;
        As[(lc + 2) * 64 + lr] = av.z; As[(lc + 3) * 64 + lr] = av.w;
        Bs[(lc + 0) * 64 + lr] = bv.x; Bs[(lc + 1) * 64 + lr] = bv.y;
        Bs[(lc + 2) * 64 + lr] = bv.z; Bs[(lc + 3) * 64 + lr] = bv.w;
        __syncthreads();
#pragma unroll
        for (int kk = 0; kk < 16; kk++) {
            float4 a = *(const float4*)&As[kk * 64 + ty * 4];
            float4 b = *(const float4*)&Bs[kk * 64 + tx * 4];
            acc[0][0] += a.x * b.x; acc[0][1] += a.x * b.y; acc[0][2] += a.x * b.z; acc[0][3] += a.x * b.w;
            acc[1][0] += a.y * b.x; acc[1][1] += a.y * b.y; acc[1][2] += a.y * b.z; acc[1][3] += a.y * b.w;
            acc[2][0] += a.z * b.x; acc[2][1] += a.z * b.y; acc[2][2] += a.z * b.z; acc[2][3] += a.z * b.w;
            acc[3][0] += a.w * b.x; acc[3][1] += a.w * b.y; acc[3][2] += a.w * b.z; acc[3][3] += a.w * b.w;
        }
    }
    float4 bb = *(const float4*)&bias[bn + tx * 4];
#pragma unroll
    for (int i = 0; i < 4; i++) {
        const int row = bm + ty * 4 + i;
        float4 o;
        o.x = acc[i][0] + bb.x; o.y = acc[i][1] + bb.y;
        o.z = acc[i][2] + bb.z; o.w = acc[i][3] + bb.w;
        if (resid) {
            float4 r = *(const float4*)&resid[(size_t)row * N + bn + tx * 4];
            o.x += r.x; o.y += r.y; o.z += r.z; o.w += r.w;
        }
        *(float4*)&C[(size_t)row * N + bn + tx * 4] = o;
    }
}

// ---------------- fused attention: scores -> exp -> attn-write + ctx --------
// block = (qtile of 64, h, b); 256 threads; unnormalized exp written to attn.
// Tiles are 64x64 = 4096 floats: each thread loads FOUR float4s (col stride 16).
#define ATTN_SMEM_FLOATS (4 * 4096 + 64 * 16)
__global__ __launch_bounds__(256) void attn_kernel(float* __restrict__ attn_out)
{
    extern __shared__ float sm[];
    float* Qt  = sm;             // [64 d][64 q]   Q transposed
    float* Kt  = sm + 4096;      // [64 d][64 k]   K chunk transposed
    float* Vs  = sm + 8192;      // [64 k][64 d]   V chunk natural
    float* Ps  = sm + 12288;     // [64 k][64 q]   P transposed
    float* red = sm + 16384;     // [64 q][16] rowsum partials

    const int t  = threadIdx.x;
    const int tx = t & 15, ty = t >> 4;
    const int qt = blockIdx.x, h = blockIdx.y, b = blockIdx.z;
    const int lr = t >> 2, lc = (t & 3) << 2;

    // load full Q tile (transposed into Qt[d][q]): 4 x float4 per thread
    {
        const float* src = g_Q + ((size_t)(b * S_) + qt * 64 + lr) * D_ + h * DK_ + lc;
#pragma unroll
        for (int j = 0; j < 4; j++) {
            const int cc = lc + j * 16;
            float4 v = *(const float4*)(src + j * 16);
            Qt[(cc + 0) * 64 + lr] = v.x; Qt[(cc + 1) * 64 + lr] = v.y;
            Qt[(cc + 2) * 64 + lr] = v.z; Qt[(cc + 3) * 64 + lr] = v.w;
        }
    }

    const float* Kb = g_K + (size_t)(b * S_) * D_ + h * DK_;
    const float* Vb = g_V + (size_t)(b * S_) * D_ + h * DK_;
    const size_t attn_row0 = (size_t)(h * B_ + b) * S_;   // head-major rows

    float c[4][4] = {};
    float rs[4]   = {};

    for (int kc = 0; kc < S_; kc += 64) {
        __syncthreads();   // prev-iter reads of Kt/Vs/Ps complete
        {
            const float* ks = Kb + (size_t)(kc + lr) * D_ + lc;
            const float* vs = Vb + (size_t)(kc + lr) * D_ + lc;
#pragma unroll
            for (int j = 0; j < 4; j++) {
                const int cc = lc + j * 16;
                float4 kv = *(const float4*)(ks + j * 16);
                Kt[(cc + 0) * 64 + lr] = kv.x; Kt[(cc + 1) * 64 + lr] = kv.y;
                Kt[(cc + 2) * 64 + lr] = kv.z; Kt[(cc + 3) * 64 + lr] = kv.w;
                float4 vv = *(const float4*)(vs + j * 16);
                *(float4*)&Vs[lr * 64 + cc] = vv;
            }
        }
        __syncthreads();

        float s[4][4] = {};
#pragma unroll
        for (int kk = 0; kk < 64; kk++) {
            float4 a  = *(const float4*)&Qt[kk * 64 + ty * 4];
            float4 bk = *(const float4*)&Kt[kk * 64 + tx * 4];
            s[0][0] += a.x * bk.x; s[0][1] += a.x * bk.y; s[0][2] += a.x * bk.z; s[0][3] += a.x * bk.w;
            s[1][0] += a.y * bk.x; s[1][1] += a.y * bk.y; s[1][2] += a.y * bk.z; s[1][3] += a.y * bk.w;
            s[2][0] += a.z * bk.x; s[2][1] += a.z * bk.y; s[2][2] += a.z * bk.z; s[2][3] += a.z * bk.w;
            s[3][0] += a.w * bk.x; s[3][1] += a.w * bk.y; s[3][2] += a.w * bk.z; s[3][3] += a.w * bk.w;
        }

#pragma unroll
        for (int i = 0; i < 4; i++) {
            const int qrow = qt * 64 + ty * 4 + i;
            uchar4 mv = *(const uchar4*)&g_mask[(size_t)(b * S_ + qrow) * S_ + kc + tx * 4];
            float p0 = mv.x ? 0.0f : __expf(s[i][0] * SCALE_);
            float p1 = mv.y ? 0.0f : __expf(s[i][1] * SCALE_);
            float p2 = mv.z ? 0.0f : __expf(s[i][2] * SCALE_);
            float p3 = mv.w ? 0.0f : __expf(s[i][3] * SCALE_);
            rs[i] += p0 + p1 + p2 + p3;
            float4 pv = make_float4(p0, p1, p2, p3);
            *(float4*)&attn_out[(attn_row0 + qrow) * S_ + kc + tx * 4] = pv;  // unnormalized
            Ps[(tx * 4 + 0) * 64 + ty * 4 + i] = p0;
            Ps[(tx * 4 + 1) * 64 + ty * 4 + i] = p1;
            Ps[(tx * 4 + 2) * 64 + ty * 4 + i] = p2;
            Ps[(tx * 4 + 3) * 64 + ty * 4 + i] = p3;
        }
        __syncthreads();

#pragma unroll
        for (int kk = 0; kk < 64; kk++) {
            float4 a  = *(const float4*)&Ps[kk * 64 + ty * 4];
            float4 vv = *(const float4*)&Vs[kk * 64 + tx * 4];
            c[0][0] += a.x * vv.x; c[0][1] += a.x * vv.y; c[0][2] += a.x * vv.z; c[0][3] += a.x * vv.w;
            c[1][0] += a.y * vv.x; c[1][1] += a.y * vv.y; c[1][2] += a.y * vv.z; c[1][3] += a.y * vv.w;
            c[2][0] += a.z * vv.x; c[2][1] += a.z * vv.y; c[2][2] += a.z * vv.z; c[2][3] += a.z * vv.w;
            c[3][0] += a.w * vv.x; c[3][1] += a.w * vv.y; c[3][2] += a.w * vv.z; c[3][3] += a.w * vv.w;
        }
    }

    // deterministic rowsum reduction: red[row][tx] partials
    __syncthreads();
#pragma unroll
    for (int i = 0; i < 4; i++) red[(ty * 4 + i) * 16 + tx] = rs[i];
    __syncthreads();
    if (t < 64) {
        float ssum = 0.0f;
#pragma unroll
        for (int j = 0; j < 16; j++) ssum += red[t * 16 + j];
        float inv = 1.0f / ssum;
        red[t * 16] = inv;
        g_inv[(size_t)(h * B_ + b) * S_ + qt * 64 + t] = inv;
    }
    __syncthreads();
#pragma unroll
    for (int i = 0; i < 4; i++) {
        const float inv = red[(ty * 4 + i) * 16];
        float4 o = make_float4(c[i][0] * inv, c[i][1] * inv, c[i][2] * inv, c[i][3] * inv);
        *(float4*)&g_ctx[((size_t)(b * S_) + qt * 64 + ty * 4 + i) * D_ + h * DK_ + tx * 4] = o;
    }
}

// ---------------- attn normalization: attn *= 1/rowsum ----------------------
__global__ __launch_bounds__(256) void norm_attn_kernel(float* __restrict__ attn)
{
    const size_t n4 = NATTN / 4;
    const size_t stride = (size_t)gridDim.x * blockDim.x;
    float4* p = (float4*)attn;
    for (size_t i = (size_t)blockIdx.x * blockDim.x + threadIdx.x; i < n4; i += stride) {
        const size_t row = i >> 9;           // (i*4)/2048
        const float inv = g_inv[row];
        float4 v = p[i];
        v.x *= inv; v.y *= inv; v.z *= inv; v.w *= inv;
        p[i] = v;
    }
}

// ---------------- layernorm --------------------------------------------------
__global__ __launch_bounds__(256) void ln_kernel(
    const float* __restrict__ X, const float* __restrict__ gamma,
    const float* __restrict__ beta, float* __restrict__ out)
{
    const int r = blockIdx.x;
    const int t = threadIdx.x;
    float4 v = *(const float4*)&X[(size_t)r * D_ + t * 4];
    float s  = v.x + v.y + v.z + v.w;
    float sq = v.x * v.x + v.y * v.y + v.z * v.z + v.w * v.w;
#pragma unroll
    for (int o = 16; o > 0; o >>= 1) {
        s  += __shfl_xor_sync(0xFFFFFFFFu, s, o);
        sq += __shfl_xor_sync(0xFFFFFFFFu, sq, o);
    }
    __shared__ float ws[8], wq[8];
    const int w = t >> 5;
    if ((t & 31) == 0) { ws[w] = s; wq[w] = sq; }
    __syncthreads();
    if (t < 32) {
        float a  = (t < 8) ? ws[t] : 0.0f;
        float b2 = (t < 8) ? wq[t] : 0.0f;
#pragma unroll
        for (int o = 4; o > 0; o >>= 1) {
            a  += __shfl_xor_sync(0xFFFFFFFFu, a, o);
            b2 += __shfl_xor_sync(0xFFFFFFFFu, b2, o);
        }
        if (t == 0) { ws[0] = a; wq[0] = b2; }
    }
    __syncthreads();
    const float mean = ws[0] * (1.0f / D_);
    const float var  = wq[0] * (1.0f / D_) - mean * mean;
    const float rstd = rsqrtf(var + LN_EPS_);
    float4 g  = *(const float4*)&gamma[t * 4];
    float4 be = *(const float4*)&beta[t * 4];
    float4 o4;
    o4.x = g.x * (v.x - mean) * rstd + be.x;
    o4.y = g.y * (v.y - mean) * rstd + be.y;
    o4.z = g.z * (v.z - mean) * rstd + be.z;
    o4.w = g.w * (v.w - mean) * rstd + be.w;
    *(float4*)&out[(size_t)r * D_ + t * 4] = o4;
}

// ---------------- launch -----------------------------------------------------
extern "C" void kernel_launch(void* const* d_in, const int* in_sizes, int n_in,
                              void* d_out, int out_size)
{
    (void)in_sizes; (void)n_in; (void)out_size;
    const float* query = (const float*)d_in[0];
    const float* key   = (const float*)d_in[1];
    const float* value = (const float*)d_in[2];
    const void*  mask  = d_in[3];
    const float* Wq = (const float*)d_in[4];
    const float* bq = (const float*)d_in[5];
    const float* Wk = (const float*)d_in[6];
    const float* bk = (const float*)d_in[7];
    const float* Wv = (const float*)d_in[8];
    const float* bv = (const float*)d_in[9];
    const float* Wo = (const float*)d_in[10];
    const float* bo = (const float*)d_in[11];
    const float* gamma = (const float*)d_in[12];
    const float* beta  = (const float*)d_in[13];

    float* out  = (float*)d_out;
    float* attn = out + BSD;

    float* gQ;   cudaGetSymbolAddress((void**)&gQ,   g_Q);
    float* gK;   cudaGetSymbolAddress((void**)&gK,   g_K);
    float* gV;   cudaGetSymbolAddress((void**)&gV,   g_V);
    float* gCtx; cudaGetSymbolAddress((void**)&gCtx, g_ctx);
    float* gOut; cudaGetSymbolAddress((void**)&gOut, g_out);

    detect_mask_kernel<<<1, 256>>>((const unsigned int*)mask);
    convert_mask_kernel<<<4096, 256>>>(mask);

    dim3 gg(D_ / 64, (B_ * S_) / 64);
    gemm_nt_kernel<<<gg, 256>>>(query, Wq, bq, nullptr, gQ, B_ * S_, D_, D_);
    gemm_nt_kernel<<<gg, 256>>>(key,   Wk, bk, nullptr, gK, B_ * S_, D_, D_);
    gemm_nt_kernel<<<gg, 256>>>(value, Wv, bv, nullptr, gV, B_ * S_, D_, D_);

    const int attn_smem = ATTN_SMEM_FLOATS * 4;
    cudaFuncSetAttribute(attn_kernel, cudaFuncAttributeMaxDynamicSharedMemorySize, attn_smem);
    attn_kernel<<<dim3(S_ / 64, H_, B_), 256, attn_smem>>>(attn);

    gemm_nt_kernel<<<gg, 256>>>(gCtx, Wo, bo, query, gOut, B_ * S_, D_, D_);

    norm_attn_kernel<<<8192, 256>>>(attn);
    ln_kernel<<<B_ * S_, 256>>>(gOut, gamma, beta, out);
}

// round 6
// speedup vs baseline: 1.9503x; 1.9503x over previous
#include <cuda_runtime.h>
#include <cstdint>

#define B_  4
#define S_  2048
#define D_  1024
#define H_  16
#define DK_ 64
#define SCALE_ 0.125f          // 1/sqrt(64)
#define LN_EPS_ 1e-5f

#define GM 8192                // B_*S_
#define GN 1024
#define GK 1024

#define BSD ((size_t)B_ * S_ * D_)            // 8,388,608
#define NMASK ((size_t)B_ * S_ * S_)          // 16,777,216

// ---------------- device scratch --------------------------------------------
__device__ float g_Q[BSD];
__device__ float g_K[BSD];
__device__ float g_V[BSD];
__device__ float g_ctx[BSD];
__device__ float g_out[BSD];
__device__ unsigned char g_mask[NMASK];
__device__ int g_mask_mode;

// ---------------- helpers ----------------------------------------------------
__device__ __forceinline__ float tf32r(float x) {
    uint32_t u; asm("cvt.rna.tf32.f32 %0, %1;" : "=r"(u) : "f"(x));
    return __uint_as_float(u);
}
__device__ __forceinline__ uint32_t uf(float x) { return __float_as_uint(x); }

__device__ __forceinline__ void mma8(float4& d, const uint32_t a[4], const uint32_t b[2]) {
    asm volatile(
        "mma.sync.aligned.m16n8k8.row.col.f32.tf32.tf32.f32 "
        "{%0,%1,%2,%3}, {%4,%5,%6,%7}, {%8,%9}, {%0,%1,%2,%3};"
        : "+f"(d.x), "+f"(d.y), "+f"(d.z), "+f"(d.w)
        : "r"(a[0]), "r"(a[1]), "r"(a[2]), "r"(a[3]), "r"(b[0]), "r"(b[1]));
}

// ---------------- mask dtype detection --------------------------------------
__global__ void detect_mask_kernel(const unsigned int* __restrict__ w) {
    __shared__ unsigned int sh;
    if (threadIdx.x == 0) sh = 0u;
    __syncthreads();
    unsigned int acc = 0u;
    for (int i = threadIdx.x; i < 65536; i += 256) acc |= w[i];
    atomicOr(&sh, acc);
    __syncthreads();
    if (threadIdx.x == 0) {
        unsigned int o = sh;
        int mode;
        if (o & 0x0000FF00u)              mode = 0; // uint8 bools
        else if ((o & 0xFFFFFF00u) == 0u) mode = 1; // int32 0/1
        else                              mode = 2; // float32 0/1
        g_mask_mode = mode;
    }
}

__global__ void convert_mask_kernel(const void* __restrict__ mptr) {
    const int mode = g_mask_mode;
    const size_t n = NMASK;
    const size_t stride = (size_t)gridDim.x * blockDim.x;
    for (size_t i = (size_t)blockIdx.x * blockDim.x + threadIdx.x; i < n; i += stride) {
        unsigned char v;
        if (mode == 0)      v = ((const unsigned char*)mptr)[i];
        else if (mode == 1) v = (unsigned char)(((const int*)mptr)[i] != 0);
        else                v = (unsigned char)(((const float*)mptr)[i] != 0.0f);
        g_mask[i] = v;
    }
}

// ---------------- tf32 tensor-core GEMM: C = A @ W^T + bias (+resid) ---------
// A:[GM,GK] rm, W:[GN,GK] rm. Block 128m x 64n, k-chunk 32. 8 warps = 4m x 2n.
// Warp tile 32m x 32n = 2 mtiles(16) x 4 ntiles(8), mma m16n8k8 tf32.
#define SA 36   // 32 + 4 pad -> conflict-free fragment LDS (banks 4g+tig)
__global__ __launch_bounds__(256) void gemm_tc(
    const float* __restrict__ A, const float* __restrict__ W,
    const float* __restrict__ bias, const float* __restrict__ resid,
    float* __restrict__ C)
{
    __shared__ float As[128 * SA];
    __shared__ float Ws[64 * SA];
    const int t = threadIdx.x;
    const int lane = t & 31, w = t >> 5;
    const int g = lane >> 2, tig = lane & 3;
    const int wq = w >> 1, wn = w & 1;
    const int bm = blockIdx.y * 128, bn = blockIdx.x * 64;
    const int lrow = t >> 3, lcol = (t & 7) * 4;

    float4 acc[2][4];
#pragma unroll
    for (int i = 0; i < 2; i++)
#pragma unroll
        for (int j = 0; j < 4; j++) acc[i][j] = make_float4(0.f, 0.f, 0.f, 0.f);

    for (int k0 = 0; k0 < GK; k0 += 32) {
        __syncthreads();
#pragma unroll
        for (int p = 0; p < 4; p++) {
            float4 v = *(const float4*)&A[(size_t)(bm + lrow + p * 32) * GK + k0 + lcol];
            float* d = &As[(lrow + p * 32) * SA + lcol];
            d[0] = tf32r(v.x); d[1] = tf32r(v.y); d[2] = tf32r(v.z); d[3] = tf32r(v.w);
        }
#pragma unroll
        for (int p = 0; p < 2; p++) {
            float4 v = *(const float4*)&W[(size_t)(bn + lrow + p * 32) * GK + k0 + lcol];
            float* d = &Ws[(lrow + p * 32) * SA + lcol];
            d[0] = tf32r(v.x); d[1] = tf32r(v.y); d[2] = tf32r(v.z); d[3] = tf32r(v.w);
        }
        __syncthreads();
#pragma unroll
        for (int ks = 0; ks < 4; ks++) {
            const int kc = ks * 8;
            uint32_t a[2][4], bfr[4][2];
#pragma unroll
            for (int i = 0; i < 2; i++) {
                const int r = 32 * wq + 16 * i + g;
                a[i][0] = uf(As[r * SA + kc + tig]);
                a[i][1] = uf(As[(r + 8) * SA + kc + tig]);
                a[i][2] = uf(As[r * SA + kc + tig + 4]);
                a[i][3] = uf(As[(r + 8) * SA + kc + tig + 4]);
            }
#pragma unroll
            for (int j = 0; j < 4; j++) {
                const int n0 = 32 * wn + 8 * j + g;
                bfr[j][0] = uf(Ws[n0 * SA + kc + tig]);
                bfr[j][1] = uf(Ws[n0 * SA + kc + tig + 4]);
            }
#pragma unroll
            for (int i = 0; i < 2; i++)
#pragma unroll
                for (int j = 0; j < 4; j++) mma8(acc[i][j], a[i], bfr[j]);
        }
    }
#pragma unroll
    for (int i = 0; i < 2; i++) {
        const int r0 = bm + 32 * wq + 16 * i + g;
#pragma unroll
        for (int j = 0; j < 4; j++) {
            const int cg = bn + 32 * wn + 8 * j + 2 * tig;
            float2 bb = *(const float2*)&bias[cg];
            float2 o0 = make_float2(acc[i][j].x + bb.x, acc[i][j].y + bb.y);
            float2 o1 = make_float2(acc[i][j].z + bb.x, acc[i][j].w + bb.y);
            if (resid) {
                float2 ra = *(const float2*)&resid[(size_t)r0 * GN + cg];
                float2 rb = *(const float2*)&resid[(size_t)(r0 + 8) * GN + cg];
                o0.x += ra.x; o0.y += ra.y; o1.x += rb.x; o1.y += rb.y;
            }
            *(float2*)&C[(size_t)r0 * GN + cg] = o0;
            *(float2*)&C[(size_t)(r0 + 8) * GN + cg] = o1;
        }
    }
}

// ---------------- tf32 tensor-core attention, two-pass -----------------------
// block = (qtile 64, h, b), 256 thr = 8 warps (4q x 2 k/d-halves).
// pass1: rowsums of exp(masked scores). pass2: recompute, normalize, write
// attn (normalized, once) + PV -> ctx (already normalized).
#define AST 68   // 64 + 4 pad
#define ATTN_SMEM_BYTES (((4 * 64 * AST) + 512 + 64) * 4 + 4096)
__global__ __launch_bounds__(256) void attn_tc(float* __restrict__ attn_out)
{
    extern __shared__ float sm[];
    float* Qs   = sm;                       // [64][AST]
    float* Ks   = sm + 64 * AST;
    float* Vs   = sm + 2 * 64 * AST;
    float* Ps   = sm + 3 * 64 * AST;
    float* red  = sm + 4 * 64 * AST;        // [64][8]
    float* invs = red + 512;                // [64]
    char*  Ms   = (char*)(invs + 64);       // [64][64] bytes

    const int t = threadIdx.x;
    const int lane = t & 31, w = t >> 5;
    const int g = lane >> 2, tig = lane & 3;
    const int wq = w >> 1, wn = w & 1;
    const int qt = blockIdx.x, h = blockIdx.y, b = blockIdx.z;
    const int qg0 = qt * 64;
    const size_t qrowg = (size_t)(b * S_) + qg0;
    const int lr = t >> 2, lc4 = (t & 3) * 4;
    const int r0 = 16 * wq + g;

    // Q tile: pre-scaled by 1/sqrt(dk), tf32-rounded
    {
        const float* Qg = g_Q + (qrowg + lr) * D_ + h * DK_;
#pragma unroll
        for (int jj = 0; jj < 4; jj++) {
            float4 v = *(const float4*)(Qg + lc4 + 16 * jj);
            float* d = &Qs[lr * AST + lc4 + 16 * jj];
            d[0] = tf32r(v.x * SCALE_); d[1] = tf32r(v.y * SCALE_);
            d[2] = tf32r(v.z * SCALE_); d[3] = tf32r(v.w * SCALE_);
        }
    }

    const float* Kb = g_K + (size_t)(b * S_) * D_ + h * DK_;
    const float* Vb = g_V + (size_t)(b * S_) * D_ + h * DK_;
    const unsigned char* Mb = g_mask + (size_t)(b * S_ + qg0) * S_;
    const size_t attn_row0 = (size_t)(h * B_ + b) * S_ + qg0;

    float rs0 = 0.f, rs1 = 0.f;

    // ---------------- pass 1: rowsums ----------------
    for (int kc = 0; kc < S_; kc += 64) {
        __syncthreads();
        {
            const float* Kg = Kb + (size_t)(kc + lr) * D_;
#pragma unroll
            for (int jj = 0; jj < 4; jj++) {
                float4 v = *(const float4*)(Kg + lc4 + 16 * jj);
                float* d = &Ks[lr * AST + lc4 + 16 * jj];
                d[0] = tf32r(v.x); d[1] = tf32r(v.y); d[2] = tf32r(v.z); d[3] = tf32r(v.w);
            }
            *(uint4*)&Ms[lr * 64 + (t & 3) * 16] =
                *(const uint4*)&Mb[(size_t)lr * S_ + kc + (t & 3) * 16];
        }
        __syncthreads();

        float4 s[4];
        s[0] = s[1] = s[2] = s[3] = make_float4(0.f, 0.f, 0.f, 0.f);
#pragma unroll
        for (int ks = 0; ks < 8; ks++) {
            const int kd = ks * 8;
            uint32_t a[4];
            a[0] = uf(Qs[r0 * AST + kd + tig]);       a[1] = uf(Qs[(r0 + 8) * AST + kd + tig]);
            a[2] = uf(Qs[r0 * AST + kd + tig + 4]);   a[3] = uf(Qs[(r0 + 8) * AST + kd + tig + 4]);
#pragma unroll
            for (int j = 0; j < 4; j++) {
                const int n0 = 32 * wn + 8 * j + g;
                uint32_t bfr[2] = { uf(Ks[n0 * AST + kd + tig]), uf(Ks[n0 * AST + kd + tig + 4]) };
                mma8(s[j], a, bfr);
            }
        }
#pragma unroll
        for (int j = 0; j < 4; j++) {
            const int c0 = 32 * wn + 8 * j + 2 * tig;
            float p0 = Ms[r0 * 64 + c0]           ? 0.f : __expf(s[j].x);
            float p1 = Ms[r0 * 64 + c0 + 1]       ? 0.f : __expf(s[j].y);
            float p2 = Ms[(r0 + 8) * 64 + c0]     ? 0.f : __expf(s[j].z);
            float p3 = Ms[(r0 + 8) * 64 + c0 + 1] ? 0.f : __expf(s[j].w);
            rs0 += p0 + p1; rs1 += p2 + p3;
        }
    }

    // rowsum reduction -> 1/sum
    __syncthreads();
    red[r0 * 8 + 4 * wn + tig] = rs0;
    red[(r0 + 8) * 8 + 4 * wn + tig] = rs1;
    __syncthreads();
    if (t < 64) {
        float ssum = 0.f;
#pragma unroll
        for (int j = 0; j < 8; j++) ssum += red[t * 8 + j];
        invs[t] = 1.0f / ssum;
    }
    __syncthreads();
    const float inv0 = invs[r0], inv1 = invs[r0 + 8];

    // ---------------- pass 2: normalized attn + ctx ----------------
    float4 o[4];
    o[0] = o[1] = o[2] = o[3] = make_float4(0.f, 0.f, 0.f, 0.f);

    for (int kc = 0; kc < S_; kc += 64) {
        __syncthreads();
        {
            const float* Kg = Kb + (size_t)(kc + lr) * D_;
            const float* Vg = Vb + (size_t)(kc + lr) * D_;
#pragma unroll
            for (int jj = 0; jj < 4; jj++) {
                float4 kv = *(const float4*)(Kg + lc4 + 16 * jj);
                float* dk = &Ks[lr * AST + lc4 + 16 * jj];
                dk[0] = tf32r(kv.x); dk[1] = tf32r(kv.y); dk[2] = tf32r(kv.z); dk[3] = tf32r(kv.w);
                float4 vv = *(const float4*)(Vg + lc4 + 16 * jj);
                float* dv = &Vs[lr * AST + lc4 + 16 * jj];
                dv[0] = tf32r(vv.x); dv[1] = tf32r(vv.y); dv[2] = tf32r(vv.z); dv[3] = tf32r(vv.w);
            }
            *(uint4*)&Ms[lr * 64 + (t & 3) * 16] =
                *(const uint4*)&Mb[(size_t)lr * S_ + kc + (t & 3) * 16];
        }
        __syncthreads();

        float4 s[4];
        s[0] = s[1] = s[2] = s[3] = make_float4(0.f, 0.f, 0.f, 0.f);
#pragma unroll
        for (int ks = 0; ks < 8; ks++) {
            const int kd = ks * 8;
            uint32_t a[4];
            a[0] = uf(Qs[r0 * AST + kd + tig]);       a[1] = uf(Qs[(r0 + 8) * AST + kd + tig]);
            a[2] = uf(Qs[r0 * AST + kd + tig + 4]);   a[3] = uf(Qs[(r0 + 8) * AST + kd + tig + 4]);
#pragma unroll
            for (int j = 0; j < 4; j++) {
                const int n0 = 32 * wn + 8 * j + g;
                uint32_t bfr[2] = { uf(Ks[n0 * AST + kd + tig]), uf(Ks[n0 * AST + kd + tig + 4]) };
                mma8(s[j], a, bfr);
            }
        }
#pragma unroll
        for (int j = 0; j < 4; j++) {
            const int c0 = 32 * wn + 8 * j + 2 * tig;
            float p0 = Ms[r0 * 64 + c0]           ? 0.f : __expf(s[j].x) * inv0;
            float p1 = Ms[r0 * 64 + c0 + 1]       ? 0.f : __expf(s[j].y) * inv0;
            float p2 = Ms[(r0 + 8) * 64 + c0]     ? 0.f : __expf(s[j].z) * inv1;
            float p3 = Ms[(r0 + 8) * 64 + c0 + 1] ? 0.f : __expf(s[j].w) * inv1;
            Ps[r0 * AST + c0]           = tf32r(p0);
            Ps[r0 * AST + c0 + 1]       = tf32r(p1);
            Ps[(r0 + 8) * AST + c0]     = tf32r(p2);
            Ps[(r0 + 8) * AST + c0 + 1] = tf32r(p3);
        }
        __syncthreads();

        // normalized attn tile -> gmem (coalesced via smem)
        {
            float* ag = attn_out + (attn_row0 + lr) * S_ + kc;
#pragma unroll
            for (int jj = 0; jj < 4; jj++)
                *(float4*)(ag + lc4 + 16 * jj) = *(const float4*)&Ps[lr * AST + lc4 + 16 * jj];
        }
        // PV: ctx += P @ V
#pragma unroll
        for (int ks = 0; ks < 8; ks++) {
            const int kd = ks * 8;
            uint32_t a[4];
            a[0] = uf(Ps[r0 * AST + kd + tig]);       a[1] = uf(Ps[(r0 + 8) * AST + kd + tig]);
            a[2] = uf(Ps[r0 * AST + kd + tig + 4]);   a[3] = uf(Ps[(r0 + 8) * AST + kd + tig + 4]);
#pragma unroll
            for (int j = 0; j < 4; j++) {
                const int d0 = 32 * wn + 8 * j + g;
                uint32_t bfr[2] = { uf(Vs[(kd + tig) * AST + d0]), uf(Vs[(kd + tig + 4) * AST + d0]) };
                mma8(o[j], a, bfr);
            }
        }
    }

    // ctx epilogue: stage via Ps then coalesced store
    __syncthreads();
#pragma unroll
    for (int j = 0; j < 4; j++) {
        const int c0 = 32 * wn + 8 * j + 2 * tig;
        Ps[r0 * AST + c0]           = o[j].x;
        Ps[r0 * AST + c0 + 1]       = o[j].y;
        Ps[(r0 + 8) * AST + c0]     = o[j].z;
        Ps[(r0 + 8) * AST + c0 + 1] = o[j].w;
    }
    __syncthreads();
    {
        float* cg = g_ctx + (qrowg + lr) * D_ + h * DK_;
#pragma unroll
        for (int jj = 0; jj < 4; jj++)
            *(float4*)(cg + lc4 + 16 * jj) = *(const float4*)&Ps[lr * AST + lc4 + 16 * jj];
    }
}

// ---------------- layernorm --------------------------------------------------
__global__ __launch_bounds__(256) void ln_kernel(
    const float* __restrict__ X, const float* __restrict__ gamma,
    const float* __restrict__ beta, float* __restrict__ out)
{
    const int r = blockIdx.x;
    const int t = threadIdx.x;
    float4 v = *(const float4*)&X[(size_t)r * D_ + t * 4];
    float s  = v.x + v.y + v.z + v.w;
    float sq = v.x * v.x + v.y * v.y + v.z * v.z + v.w * v.w;
#pragma unroll
    for (int o = 16; o > 0; o >>= 1) {
        s  += __shfl_xor_sync(0xFFFFFFFFu, s, o);
        sq += __shfl_xor_sync(0xFFFFFFFFu, sq, o);
    }
    __shared__ float ws[8], wqv[8];
    const int w = t >> 5;
    if ((t & 31) == 0) { ws[w] = s; wqv[w] = sq; }
    __syncthreads();
    if (t < 32) {
        float a  = (t < 8) ? ws[t] : 0.0f;
        float b2 = (t < 8) ? wqv[t] : 0.0f;
#pragma unroll
        for (int o = 4; o > 0; o >>= 1) {
            a  += __shfl_xor_sync(0xFFFFFFFFu, a, o);
            b2 += __shfl_xor_sync(0xFFFFFFFFu, b2, o);
        }
        if (t == 0) { ws[0] = a; wqv[0] = b2; }
    }
    __syncthreads();
    const float mean = ws[0] * (1.0f / D_);
    const float var  = wqv[0] * (1.0f / D_) - mean * mean;
    const float rstd = rsqrtf(var + LN_EPS_);
    float4 gm = *(const float4*)&gamma[t * 4];
    float4 be = *(const float4*)&beta[t * 4];
    float4 o4;
    o4.x = gm.x * (v.x - mean) * rstd + be.x;
    o4.y = gm.y * (v.y - mean) * rstd + be.y;
    o4.z = gm.z * (v.z - mean) * rstd + be.z;
    o4.w = gm.w * (v.w - mean) * rstd + be.w;
    *(float4*)&out[(size_t)r * D_ + t * 4] = o4;
}

// ---------------- launch -----------------------------------------------------
extern "C" void kernel_launch(void* const* d_in, const int* in_sizes, int n_in,
                              void* d_out, int out_size)
{
    (void)in_sizes; (void)n_in; (void)out_size;
    const float* query = (const float*)d_in[0];
    const float* key   = (const float*)d_in[1];
    const float* value = (const float*)d_in[2];
    const void*  mask  = d_in[3];
    const float* Wq = (const float*)d_in[4];
    const float* bq = (const float*)d_in[5];
    const float* Wk = (const float*)d_in[6];
    const float* bk = (const float*)d_in[7];
    const float* Wv = (const float*)d_in[8];
    const float* bv = (const float*)d_in[9];
    const float* Wo = (const float*)d_in[10];
    const float* bo = (const float*)d_in[11];
    const float* gamma = (const float*)d_in[12];
    const float* beta  = (const float*)d_in[13];

    float* out  = (float*)d_out;
    float* attn = out + BSD;

    float* gQ;   cudaGetSymbolAddress((void**)&gQ,   g_Q);
    float* gK;   cudaGetSymbolAddress((void**)&gK,   g_K);
    float* gV;   cudaGetSymbolAddress((void**)&gV,   g_V);
    float* gCtx; cudaGetSymbolAddress((void**)&gCtx, g_ctx);
    float* gOut; cudaGetSymbolAddress((void**)&gOut, g_out);

    detect_mask_kernel<<<1, 256>>>((const unsigned int*)mask);
    convert_mask_kernel<<<4096, 256>>>(mask);

    dim3 gg(GN / 64, GM / 128);
    gemm_tc<<<gg, 256>>>(query, Wq, bq, nullptr, gQ);
    gemm_tc<<<gg, 256>>>(key,   Wk, bk, nullptr, gK);
    gemm_tc<<<gg, 256>>>(value, Wv, bv, nullptr, gV);

    cudaFuncSetAttribute(attn_tc, cudaFuncAttributeMaxDynamicSharedMemorySize, ATTN_SMEM_BYTES);
    attn_tc<<<dim3(S_ / 64, H_, B_), 256, ATTN_SMEM_BYTES>>>(attn);

    gemm_tc<<<gg, 256>>>(gCtx, Wo, bo, query, gOut);

    ln_kernel<<<B_ * S_, 256>>>(gOut, gamma, beta, out);
}

// round 7
// speedup vs baseline: 1.9515x; 1.0006x over previous
#include <cuda_runtime.h>
#include <cstdint>

#define B_  4
#define S_  2048
#define D_  1024
#define H_  16
#define DK_ 64
#define SCALE_ 0.125f          // 1/sqrt(64)
#define LN_EPS_ 1e-5f

#define GM 8192                // B_*S_
#define GN 1024
#define GK 1024

#define BSD ((size_t)B_ * S_ * D_)            // 8,388,608
#define NMASK ((size_t)B_ * S_ * S_)          // 16,777,216

// ---------------- device scratch --------------------------------------------
__device__ float g_Q[BSD];
__device__ float g_K[BSD];
__device__ float g_V[BSD];
__device__ float g_ctx[BSD];
__device__ float g_out[BSD];
__device__ unsigned char g_mask[NMASK];
__device__ int g_mask_mode;

// ---------------- helpers ----------------------------------------------------
__device__ __forceinline__ float tf32r(float x) {
    uint32_t u; asm("cvt.rna.tf32.f32 %0, %1;" : "=r"(u) : "f"(x));
    return __uint_as_float(u);
}
__device__ __forceinline__ uint32_t uf(float x) { return __float_as_uint(x); }

__device__ __forceinline__ void mma8(float4& d, const uint32_t a[4], const uint32_t b[2]) {
    asm volatile(
        "mma.sync.aligned.m16n8k8.row.col.f32.tf32.tf32.f32 "
        "{%0,%1,%2,%3}, {%4,%5,%6,%7}, {%8,%9}, {%0,%1,%2,%3};"
        : "+f"(d.x), "+f"(d.y), "+f"(d.z), "+f"(d.w)
        : "r"(a[0]), "r"(a[1]), "r"(a[2]), "r"(a[3]), "r"(b[0]), "r"(b[1]));
}

// ---------------- mask dtype detection --------------------------------------
__global__ void detect_mask_kernel(const unsigned int* __restrict__ w) {
    __shared__ unsigned int sh;
    if (threadIdx.x == 0) sh = 0u;
    __syncthreads();
    unsigned int acc = 0u;
    for (int i = threadIdx.x; i < 65536; i += 256) acc |= w[i];
    atomicOr(&sh, acc);
    __syncthreads();
    if (threadIdx.x == 0) {
        unsigned int o = sh;
        int mode;
        if (o & 0x0000FF00u)              mode = 0; // uint8 bools
        else if ((o & 0xFFFFFF00u) == 0u) mode = 1; // int32 0/1
        else                              mode = 2; // float32 0/1
        g_mask_mode = mode;
    }
}

__global__ void convert_mask_kernel(const void* __restrict__ mptr) {
    const int mode = g_mask_mode;
    const size_t n = NMASK;
    const size_t stride = (size_t)gridDim.x * blockDim.x;
    for (size_t i = (size_t)blockIdx.x * blockDim.x + threadIdx.x; i < n; i += stride) {
        unsigned char v;
        if (mode == 0)      v = ((const unsigned char*)mptr)[i];
        else if (mode == 1) v = (unsigned char)(((const int*)mptr)[i] != 0);
        else                v = (unsigned char)(((const float*)mptr)[i] != 0.0f);
        g_mask[i] = v;
    }
}

// ---------------- tf32 tensor-core GEMM: C = A @ W^T + bias (+resid) ---------
// Block 128m x 128n, k-chunk 32. 8 warps = 4m x 2n; warp tile 32m x 64n.
#define SA 36   // 32 + 4 pad -> conflict-free fragment LDS
__global__ __launch_bounds__(256, 2) void gemm_tc(
    const float* __restrict__ A, const float* __restrict__ W,
    const float* __restrict__ bias, const float* __restrict__ resid,
    float* __restrict__ C)
{
    __shared__ float As[128 * SA];
    __shared__ float Ws[128 * SA];
    const int t = threadIdx.x;
    const int lane = t & 31, w = t >> 5;
    const int g = lane >> 2, tig = lane & 3;
    const int wq = w >> 1, wn = w & 1;
    const int bm = blockIdx.y * 128, bn = blockIdx.x * 128;
    const int lrow = t >> 1, lseg = (t & 1) * 16;

    float4 acc[2][8];
#pragma unroll
    for (int i = 0; i < 2; i++)
#pragma unroll
        for (int j = 0; j < 8; j++) acc[i][j] = make_float4(0.f, 0.f, 0.f, 0.f);

    for (int k0 = 0; k0 < GK; k0 += 32) {
        __syncthreads();
        {
            const float* Ag = A + (size_t)(bm + lrow) * GK + k0 + lseg;
            float* d = &As[lrow * SA + lseg];
#pragma unroll
            for (int p = 0; p < 4; p++) {
                float4 v = *(const float4*)(Ag + 4 * p);
                float4 c = make_float4(tf32r(v.x), tf32r(v.y), tf32r(v.z), tf32r(v.w));
                *(float4*)(d + 4 * p) = c;
            }
            const float* Wg = W + (size_t)(bn + lrow) * GK + k0 + lseg;
            float* dw = &Ws[lrow * SA + lseg];
#pragma unroll
            for (int p = 0; p < 4; p++) {
                float4 v = *(const float4*)(Wg + 4 * p);
                float4 c = make_float4(tf32r(v.x), tf32r(v.y), tf32r(v.z), tf32r(v.w));
                *(float4*)(dw + 4 * p) = c;
            }
        }
        __syncthreads();
#pragma unroll
        for (int ks = 0; ks < 4; ks++) {
            const int kc = ks * 8;
            uint32_t a[2][4], bfr[8][2];
#pragma unroll
            for (int i = 0; i < 2; i++) {
                const int r = 32 * wq + 16 * i + g;
                a[i][0] = uf(As[r * SA + kc + tig]);
                a[i][1] = uf(As[(r + 8) * SA + kc + tig]);
                a[i][2] = uf(As[r * SA + kc + tig + 4]);
                a[i][3] = uf(As[(r + 8) * SA + kc + tig + 4]);
            }
#pragma unroll
            for (int j = 0; j < 8; j++) {
                const int n0 = 64 * wn + 8 * j + g;
                bfr[j][0] = uf(Ws[n0 * SA + kc + tig]);
                bfr[j][1] = uf(Ws[n0 * SA + kc + tig + 4]);
            }
#pragma unroll
            for (int i = 0; i < 2; i++)
#pragma unroll
                for (int j = 0; j < 8; j++) mma8(acc[i][j], a[i], bfr[j]);
        }
    }
#pragma unroll
    for (int i = 0; i < 2; i++) {
        const int r0 = bm + 32 * wq + 16 * i + g;
#pragma unroll
        for (int j = 0; j < 8; j++) {
            const int cg = bn + 64 * wn + 8 * j + 2 * tig;
            float2 bb = *(const float2*)&bias[cg];
            float2 o0 = make_float2(acc[i][j].x + bb.x, acc[i][j].y + bb.y);
            float2 o1 = make_float2(acc[i][j].z + bb.x, acc[i][j].w + bb.y);
            if (resid) {
                float2 ra = *(const float2*)&resid[(size_t)r0 * GN + cg];
                float2 rb = *(const float2*)&resid[(size_t)(r0 + 8) * GN + cg];
                o0.x += ra.x; o0.y += ra.y; o1.x += rb.x; o1.y += rb.y;
            }
            *(float2*)&C[(size_t)r0 * GN + cg] = o0;
            *(float2*)&C[(size_t)(r0 + 8) * GN + cg] = o1;
        }
    }
}

// ---------------- tf32 tensor-core attention, two-pass, qtile=128 ------------
// 8 warps (4q x 2 kn halves), warp tile 32q x 32k. Q fragments in registers
// (loaded once, used by both passes). Pass2 writes normalized attn + ctx.
#define AST 68   // Q/K/P stride
#define VST 72   // V stride (conflict-free PV B-frags: bank 8*tig+g)
// smem float offsets
#define OFF_PS  0
#define OFF_KS  (128 * AST)                    // 8704
#define OFF_VS  (OFF_KS + 64 * AST)            // 13056
#define OFF_RED (OFF_VS + 64 * VST)            // 17664
#define OFF_INV (OFF_RED + 128 * 8)            // 18688
#define OFF_MS  (OFF_INV + 128)                // 18816 (floats) -> mask bytes
#define ATTN_SMEM_BYTES (OFF_MS * 4 + 128 * 64)
__global__ __launch_bounds__(256) void attn_tc(float* __restrict__ attn_out)
{
    extern __shared__ float sm[];
    float* Ps   = sm + OFF_PS;
    float* Ks   = sm + OFF_KS;
    float* Vs   = sm + OFF_VS;
    float* red  = sm + OFF_RED;
    float* invs = sm + OFF_INV;
    char*  Ms   = (char*)(sm + OFF_MS);

    const int t = threadIdx.x;
    const int lane = t & 31, w = t >> 5;
    const int g = lane >> 2, tig = lane & 3;
    const int wq = w >> 1, wn = w & 1;
    const int qt = blockIdx.x, h = blockIdx.y, b = blockIdx.z;
    const int qg0 = qt * 128;
    const size_t qrowg = (size_t)(b * S_) + qg0;
    const int lr = t >> 1, half = t & 1;          // 128-row ops
    const int kr = t >> 2, kc4 = (t & 3) * 16;    // 64-row ops

    // ---- stage Q (scaled, tf32-rounded) into Ps, then lift fragments to regs
    {
        const float* Qg = g_Q + (qrowg + lr) * D_ + h * DK_ + half * 32;
        float* dst = &Ps[lr * AST + half * 32];
#pragma unroll
        for (int jj = 0; jj < 8; jj++) {
            float4 v = *(const float4*)(Qg + 4 * jj);
            float4 c = make_float4(tf32r(v.x * SCALE_), tf32r(v.y * SCALE_),
                                   tf32r(v.z * SCALE_), tf32r(v.w * SCALE_));
            *(float4*)(dst + 4 * jj) = c;
        }
    }
    __syncthreads();
    uint32_t qa[2][8][4];
#pragma unroll
    for (int i = 0; i < 2; i++) {
        const int r = 32 * wq + 16 * i + g;
#pragma unroll
        for (int ks = 0; ks < 8; ks++) {
            const int kd = ks * 8;
            qa[i][ks][0] = uf(Ps[r * AST + kd + tig]);
            qa[i][ks][1] = uf(Ps[(r + 8) * AST + kd + tig]);
            qa[i][ks][2] = uf(Ps[r * AST + kd + tig + 4]);
            qa[i][ks][3] = uf(Ps[(r + 8) * AST + kd + tig + 4]);
        }
    }

    const float* Kb = g_K + (size_t)(b * S_) * D_ + h * DK_;
    const float* Vb = g_V + (size_t)(b * S_) * D_ + h * DK_;
    const unsigned char* Mb = g_mask + (size_t)(b * S_ + qg0) * S_;
    const size_t attn_row0 = (size_t)(h * B_ + b) * S_ + qg0;

    float rs[2][2] = {{0.f, 0.f}, {0.f, 0.f}};

    // ---------------- pass 1: rowsums ----------------
    for (int kc = 0; kc < S_; kc += 64) {
        __syncthreads();
        {
            const float* Kg = Kb + (size_t)(kc + kr) * D_ + kc4;
            float* dk = &Ks[kr * AST + kc4];
#pragma unroll
            for (int jj = 0; jj < 4; jj++) {
                float4 v = *(const float4*)(Kg + 4 * jj);
                float4 c = make_float4(tf32r(v.x), tf32r(v.y), tf32r(v.z), tf32r(v.w));
                *(float4*)(dk + 4 * jj) = c;
            }
            const unsigned char* mg = Mb + (size_t)lr * S_ + kc + half * 32;
            *(uint4*)&Ms[lr * 64 + half * 32]      = *(const uint4*)(mg);
            *(uint4*)&Ms[lr * 64 + half * 32 + 16] = *(const uint4*)(mg + 16);
        }
        __syncthreads();

        float4 s[2][4];
#pragma unroll
        for (int i = 0; i < 2; i++)
#pragma unroll
            for (int j = 0; j < 4; j++) s[i][j] = make_float4(0.f, 0.f, 0.f, 0.f);
#pragma unroll
        for (int ks = 0; ks < 8; ks++) {
            const int kd = ks * 8;
            uint32_t bf[4][2];
#pragma unroll
            for (int j = 0; j < 4; j++) {
                const int n0 = 32 * wn + 8 * j + g;
                bf[j][0] = uf(Ks[n0 * AST + kd + tig]);
                bf[j][1] = uf(Ks[n0 * AST + kd + tig + 4]);
            }
#pragma unroll
            for (int i = 0; i < 2; i++)
#pragma unroll
                for (int j = 0; j < 4; j++) mma8(s[i][j], qa[i][ks], bf[j]);
        }
#pragma unroll
        for (int i = 0; i < 2; i++) {
            const int r = 32 * wq + 16 * i + g;
#pragma unroll
            for (int j = 0; j < 4; j++) {
                const int c0 = 32 * wn + 8 * j + 2 * tig;
                float p0 = Ms[r * 64 + c0]           ? 0.f : __expf(s[i][j].x);
                float p1 = Ms[r * 64 + c0 + 1]       ? 0.f : __expf(s[i][j].y);
                float p2 = Ms[(r + 8) * 64 + c0]     ? 0.f : __expf(s[i][j].z);
                float p3 = Ms[(r + 8) * 64 + c0 + 1] ? 0.f : __expf(s[i][j].w);
                rs[i][0] += p0 + p1; rs[i][1] += p2 + p3;
            }
        }
    }

    // rowsum reduction -> 1/sum
    __syncthreads();
#pragma unroll
    for (int i = 0; i < 2; i++) {
        const int r = 32 * wq + 16 * i + g;
        red[r * 8 + wn * 4 + tig]       = rs[i][0];
        red[(r + 8) * 8 + wn * 4 + tig] = rs[i][1];
    }
    __syncthreads();
    if (t < 128) {
        float ssum = 0.f;
#pragma unroll
        for (int j = 0; j < 8; j++) ssum += red[t * 8 + j];
        invs[t] = 1.0f / ssum;
    }
    __syncthreads();
    float inv[2][2];
#pragma unroll
    for (int i = 0; i < 2; i++) {
        const int r = 32 * wq + 16 * i + g;
        inv[i][0] = invs[r]; inv[i][1] = invs[r + 8];
    }

    // ---------------- pass 2: normalized attn + ctx ----------------
    float4 o[2][4];
#pragma unroll
    for (int i = 0; i < 2; i++)
#pragma unroll
        for (int j = 0; j < 4; j++) o[i][j] = make_float4(0.f, 0.f, 0.f, 0.f);

    for (int kc = 0; kc < S_; kc += 64) {
        __syncthreads();
        {
            const float* Kg = Kb + (size_t)(kc + kr) * D_ + kc4;
            const float* Vg = Vb + (size_t)(kc + kr) * D_ + kc4;
            float* dk = &Ks[kr * AST + kc4];
            float* dv = &Vs[kr * VST + kc4];
#pragma unroll
            for (int jj = 0; jj < 4; jj++) {
                float4 v = *(const float4*)(Kg + 4 * jj);
                float4 c = make_float4(tf32r(v.x), tf32r(v.y), tf32r(v.z), tf32r(v.w));
                *(float4*)(dk + 4 * jj) = c;
                float4 vv = *(const float4*)(Vg + 4 * jj);
                float4 cv = make_float4(tf32r(vv.x), tf32r(vv.y), tf32r(vv.z), tf32r(vv.w));
                *(float4*)(dv + 4 * jj) = cv;
            }
            const unsigned char* mg = Mb + (size_t)lr * S_ + kc + half * 32;
            *(uint4*)&Ms[lr * 64 + half * 32]      = *(const uint4*)(mg);
            *(uint4*)&Ms[lr * 64 + half * 32 + 16] = *(const uint4*)(mg + 16);
        }
        __syncthreads();

        float4 s[2][4];
#pragma unroll
        for (int i = 0; i < 2; i++)
#pragma unroll
            for (int j = 0; j < 4; j++) s[i][j] = make_float4(0.f, 0.f, 0.f, 0.f);
#pragma unroll
        for (int ks = 0; ks < 8; ks++) {
            const int kd = ks * 8;
            uint32_t bf[4][2];
#pragma unroll
            for (int j = 0; j < 4; j++) {
                const int n0 = 32 * wn + 8 * j + g;
                bf[j][0] = uf(Ks[n0 * AST + kd + tig]);
                bf[j][1] = uf(Ks[n0 * AST + kd + tig + 4]);
            }
#pragma unroll
            for (int i = 0; i < 2; i++)
#pragma unroll
                for (int j = 0; j < 4; j++) mma8(s[i][j], qa[i][ks], bf[j]);
        }
#pragma unroll
        for (int i = 0; i < 2; i++) {
            const int r = 32 * wq + 16 * i + g;
#pragma unroll
            for (int j = 0; j < 4; j++) {
                const int c0 = 32 * wn + 8 * j + 2 * tig;
                float p0 = Ms[r * 64 + c0]           ? 0.f : __expf(s[i][j].x) * inv[i][0];
                float p1 = Ms[r * 64 + c0 + 1]       ? 0.f : __expf(s[i][j].y) * inv[i][0];
                float p2 = Ms[(r + 8) * 64 + c0]     ? 0.f : __expf(s[i][j].z) * inv[i][1];
                float p3 = Ms[(r + 8) * 64 + c0 + 1] ? 0.f : __expf(s[i][j].w) * inv[i][1];
                Ps[r * AST + c0]           = tf32r(p0);
                Ps[r * AST + c0 + 1]       = tf32r(p1);
                Ps[(r + 8) * AST + c0]     = tf32r(p2);
                Ps[(r + 8) * AST + c0 + 1] = tf32r(p3);
            }
        }
        __syncthreads();

        // normalized attn tile -> gmem (coalesced from Ps)
        {
            float* ag = attn_out + (attn_row0 + lr) * S_ + kc + half * 32;
            const float* src = &Ps[lr * AST + half * 32];
#pragma unroll
            for (int jj = 0; jj < 8; jj++)
                *(float4*)(ag + 4 * jj) = *(const float4*)(src + 4 * jj);
        }
        // PV: ctx += P @ V (P normalized -> ctx final)
#pragma unroll
        for (int ks = 0; ks < 8; ks++) {
            const int kd = ks * 8;
            uint32_t pa[2][4], vb[4][2];
#pragma unroll
            for (int i = 0; i < 2; i++) {
                const int r = 32 * wq + 16 * i + g;
                pa[i][0] = uf(Ps[r * AST + kd + tig]);
                pa[i][1] = uf(Ps[(r + 8) * AST + kd + tig]);
                pa[i][2] = uf(Ps[r * AST + kd + tig + 4]);
                pa[i][3] = uf(Ps[(r + 8) * AST + kd + tig + 4]);
            }
#pragma unroll
            for (int j = 0; j < 4; j++) {
                const int d0 = 32 * wn + 8 * j + g;
                vb[j][0] = uf(Vs[(kd + tig) * VST + d0]);
                vb[j][1] = uf(Vs[(kd + tig + 4) * VST + d0]);
            }
#pragma unroll
            for (int i = 0; i < 2; i++)
#pragma unroll
                for (int j = 0; j < 4; j++) mma8(o[i][j], pa[i], vb[j]);
        }
    }

    // ctx epilogue: stage via Ps, coalesced store
    __syncthreads();
#pragma unroll
    for (int i = 0; i < 2; i++) {
        const int r = 32 * wq + 16 * i + g;
#pragma unroll
        for (int j = 0; j < 4; j++) {
            const int c0 = 32 * wn + 8 * j + 2 * tig;
            Ps[r * AST + c0]           = o[i][j].x;
            Ps[r * AST + c0 + 1]       = o[i][j].y;
            Ps[(r + 8) * AST + c0]     = o[i][j].z;
            Ps[(r + 8) * AST + c0 + 1] = o[i][j].w;
        }
    }
    __syncthreads();
    {
        float* cg = g_ctx + (qrowg + lr) * D_ + h * DK_ + half * 32;
        const float* src = &Ps[lr * AST + half * 32];
#pragma unroll
        for (int jj = 0; jj < 8; jj++)
            *(float4*)(cg + 4 * jj) = *(const float4*)(src + 4 * jj);
    }
}

// ---------------- layernorm --------------------------------------------------
__global__ __launch_bounds__(256) void ln_kernel(
    const float* __restrict__ X, const float* __restrict__ gamma,
    const float* __restrict__ beta, float* __restrict__ out)
{
    const int r = blockIdx.x;
    const int t = threadIdx.x;
    float4 v = *(const float4*)&X[(size_t)r * D_ + t * 4];
    float s  = v.x + v.y + v.z + v.w;
    float sq = v.x * v.x + v.y * v.y + v.z * v.z + v.w * v.w;
#pragma unroll
    for (int o = 16; o > 0; o >>= 1) {
        s  += __shfl_xor_sync(0xFFFFFFFFu, s, o);
        sq += __shfl_xor_sync(0xFFFFFFFFu, sq, o);
    }
    __shared__ float ws[8], wqv[8];
    const int w = t >> 5;
    if ((t & 31) == 0) { ws[w] = s; wqv[w] = sq; }
    __syncthreads();
    if (t < 32) {
        float a  = (t < 8) ? ws[t] : 0.0f;
        float b2 = (t < 8) ? wqv[t] : 0.0f;
#pragma unroll
        for (int o = 4; o > 0; o >>= 1) {
            a  += __shfl_xor_sync(0xFFFFFFFFu, a, o);
            b2 += __shfl_xor_sync(0xFFFFFFFFu, b2, o);
        }
        if (t == 0) { ws[0] = a; wqv[0] = b2; }
    }
    __syncthreads();
    const float mean = ws[0] * (1.0f / D_);
    const float var  = wqv[0] * (1.0f / D_) - mean * mean;
    const float rstd = rsqrtf(var + LN_EPS_);
    float4 gm = *(const float4*)&gamma[t * 4];
    float4 be = *(const float4*)&beta[t * 4];
    float4 o4;
    o4.x = gm.x * (v.x - mean) * rstd + be.x;
    o4.y = gm.y * (v.y - mean) * rstd + be.y;
    o4.z = gm.z * (v.z - mean) * rstd + be.z;
    o4.w = gm.w * (v.w - mean) * rstd + be.w;
    *(float4*)&out[(size_t)r * D_ + t * 4] = o4;
}

// ---------------- launch -----------------------------------------------------
extern "C" void kernel_launch(void* const* d_in, const int* in_sizes, int n_in,
                              void* d_out, int out_size)
{
    (void)in_sizes; (void)n_in; (void)out_size;
    const float* query = (const float*)d_in[0];
    const float* key   = (const float*)d_in[1];
    const float* value = (const float*)d_in[2];
    const void*  mask  = d_in[3];
    const float* Wq = (const float*)d_in[4];
    const float* bq = (const float*)d_in[5];
    const float* Wk = (const float*)d_in[6];
    const float* bk = (const float*)d_in[7];
    const float* Wv = (const float*)d_in[8];
    const float* bv = (const float*)d_in[9];
    const float* Wo = (const float*)d_in[10];
    const float* bo = (const float*)d_in[11];
    const float* gamma = (const float*)d_in[12];
    const float* beta  = (const float*)d_in[13];

    float* out  = (float*)d_out;
    float* attn = out + BSD;

    float* gQ;   cudaGetSymbolAddress((void**)&gQ,   g_Q);
    float* gK;   cudaGetSymbolAddress((void**)&gK,   g_K);
    float* gV;   cudaGetSymbolAddress((void**)&gV,   g_V);
    float* gCtx; cudaGetSymbolAddress((void**)&gCtx, g_ctx);
    float* gOut; cudaGetSymbolAddress((void**)&gOut, g_out);

    detect_mask_kernel<<<1, 256>>>((const unsigned int*)mask);
    convert_mask_kernel<<<4096, 256>>>(mask);

    dim3 gg(GN / 128, GM / 128);
    gemm_tc<<<gg, 256>>>(query, Wq, bq, nullptr, gQ);
    gemm_tc<<<gg, 256>>>(key,   Wk, bk, nullptr, gK);
    gemm_tc<<<gg, 256>>>(value, Wv, bv, nullptr, gV);

    cudaFuncSetAttribute(attn_tc, cudaFuncAttributeMaxDynamicSharedMemorySize, ATTN_SMEM_BYTES);
    attn_tc<<<dim3(S_ / 128, H_, B_), 256, ATTN_SMEM_BYTES>>>(attn);

    gemm_tc<<<gg, 256>>>(gCtx, Wo, bo, query, gOut);

    ln_kernel<<<B_ * S_, 256>>>(gOut, gamma, beta, out);
}

// round 9
// speedup vs baseline: 2.3942x; 1.2268x over previous
#include <cuda_runtime.h>
#include <cstdint>

#define B_  4
#define S_  2048
#define D_  1024
#define H_  16
#define DK_ 64
#define SCALE_ 0.125f          // 1/sqrt(64), exact power of two
#define LN_EPS_ 1e-5f

#define GM 8192                // B_*S_
#define GN 1024
#define GK 1024

#define BSD ((size_t)B_ * S_ * D_)            // 8,388,608
#define NMASK ((size_t)B_ * S_ * S_)          // 16,777,216
#define NATTN ((size_t)B_ * H_ * S_ * S_)     // 268,435,456

// ---------------- device scratch --------------------------------------------
__device__ float g_Q[BSD];
__device__ float g_K[BSD];
__device__ float g_V[BSD];
__device__ float g_ctx[BSD];
__device__ float g_out[BSD];
__device__ float g_Wr[(size_t)D_ * D_];
__device__ float g_inv[(size_t)B_ * H_ * S_];
__device__ unsigned char g_mask[NMASK];
__device__ int g_mask_mode;

// ---------------- helpers ----------------------------------------------------
__device__ __forceinline__ float tf32r(float x) {
    uint32_t u; asm("cvt.rna.tf32.f32 %0, %1;" : "=r"(u) : "f"(x));
    return __uint_as_float(u);
}
__device__ __forceinline__ uint32_t uf(float x) { return __float_as_uint(x); }

__device__ __forceinline__ void mma8(float4& d, const uint32_t a[4], const uint32_t b[2]) {
    asm volatile(
        "mma.sync.aligned.m16n8k8.row.col.f32.tf32.tf32.f32 "
        "{%0,%1,%2,%3}, {%4,%5,%6,%7}, {%8,%9}, {%0,%1,%2,%3};"
        : "+f"(d.x), "+f"(d.y), "+f"(d.z), "+f"(d.w)
        : "r"(a[0]), "r"(a[1]), "r"(a[2]), "r"(a[3]), "r"(b[0]), "r"(b[1]));
}

__device__ __forceinline__ void cpa16(void* s, const void* g) {
    uint32_t sa = (uint32_t)__cvta_generic_to_shared(s);
    asm volatile("cp.async.ca.shared.global [%0], [%1], 16;" :: "r"(sa), "l"(g));
}
__device__ __forceinline__ void cpa_commit() { asm volatile("cp.async.commit_group;"); }
__device__ __forceinline__ void cpa_wait0()  { asm volatile("cp.async.wait_group 0;"); }

// ---------------- tf32 pre-round (RNA) ---------------------------------------
__global__ __launch_bounds__(256) void round_copy(const float* __restrict__ src,
                                                  float* __restrict__ dst, size_t n4)
{
    const size_t stride = (size_t)gridDim.x * blockDim.x;
    const float4* s4 = (const float4*)src;
    float4* d4 = (float4*)dst;
    for (size_t i = (size_t)blockIdx.x * blockDim.x + threadIdx.x; i < n4; i += stride) {
        float4 v = s4[i];
        d4[i] = make_float4(tf32r(v.x), tf32r(v.y), tf32r(v.z), tf32r(v.w));
    }
}

// ---------------- mask dtype detection --------------------------------------
__global__ void detect_mask_kernel(const unsigned int* __restrict__ w) {
    __shared__ unsigned int sh;
    if (threadIdx.x == 0) sh = 0u;
    __syncthreads();
    unsigned int acc = 0u;
    for (int i = threadIdx.x; i < 65536; i += 256) acc |= w[i];
    atomicOr(&sh, acc);
    __syncthreads();
    if (threadIdx.x == 0) {
        unsigned int o = sh;
        int mode;
        if (o & 0x0000FF00u)              mode = 0; // uint8 bools
        else if ((o & 0xFFFFFF00u) == 0u) mode = 1; // int32 0/1
        else                              mode = 2; // float32 0/1
        g_mask_mode = mode;
    }
}

__global__ void convert_mask_kernel(const void* __restrict__ mptr) {
    const int mode = g_mask_mode;
    const size_t n = NMASK;
    const size_t stride = (size_t)gridDim.x * blockDim.x;
    for (size_t i = (size_t)blockIdx.x * blockDim.x + threadIdx.x; i < n; i += stride) {
        unsigned char v;
        if (mode == 0)      v = ((const unsigned char*)mptr)[i];
        else if (mode == 1) v = (unsigned char)(((const int*)mptr)[i] != 0);
        else                v = (unsigned char)(((const float*)mptr)[i] != 0.0f);
        g_mask[i] = v;
    }
}

// ---------------- tf32 TC GEMM, cp.async double-buffered ---------------------
// C = A @ W^T + bias (+resid). A,W pre-rounded tf32. Block 128x128, kc=32.
// 8 warps = 4m x 2n, warp tile 32x64. DYNAMIC smem (73.7KB > 48KB static cap).
#define SA 36
#define GEMM_SMEM_BYTES (2 * 2 * 128 * SA * 4)   // 73728
__global__ __launch_bounds__(256, 2) void gemm_tc(
    const float* __restrict__ A, const float* __restrict__ W,
    const float* __restrict__ bias, const float* __restrict__ resid,
    float* __restrict__ C, int round_out)
{
    extern __shared__ float gsm[];
    float* Asb = gsm;                      // 2 stages x 128*SA
    float* Wsb = gsm + 2 * 128 * SA;
    const int t = threadIdx.x;
    const int lane = t & 31, w = t >> 5;
    const int g = lane >> 2, tig = lane & 3;
    const int wq = w >> 1, wn = w & 1;
    const int bm = blockIdx.y * 128, bn = blockIdx.x * 128;
    const int lrow = t >> 1, lseg = (t & 1) * 16;

    const float* Ag = A + (size_t)(bm + lrow) * GK + lseg;
    const float* Wg = W + (size_t)(bn + lrow) * GK + lseg;

    float4 acc[2][8];
#pragma unroll
    for (int i = 0; i < 2; i++)
#pragma unroll
        for (int j = 0; j < 8; j++) acc[i][j] = make_float4(0.f, 0.f, 0.f, 0.f);

    // preload stage 0
    {
        float* da = Asb + lrow * SA + lseg;
        float* dw = Wsb + lrow * SA + lseg;
#pragma unroll
        for (int p = 0; p < 4; p++) { cpa16(da + 4 * p, Ag + 4 * p); cpa16(dw + 4 * p, Wg + 4 * p); }
        cpa_commit();
    }

    for (int it = 0; it < GK / 32; it++) {
        cpa_wait0();
        __syncthreads();
        if (it + 1 < GK / 32) {
            const int k0 = (it + 1) * 32;
            const int st = (it + 1) & 1;
            float* da = Asb + st * (128 * SA) + lrow * SA + lseg;
            float* dw = Wsb + st * (128 * SA) + lrow * SA + lseg;
#pragma unroll
            for (int p = 0; p < 4; p++) { cpa16(da + 4 * p, Ag + k0 + 4 * p); cpa16(dw + 4 * p, Wg + k0 + 4 * p); }
            cpa_commit();
        }
        const float* as = Asb + (it & 1) * (128 * SA);
        const float* ws = Wsb + (it & 1) * (128 * SA);
#pragma unroll
        for (int ks = 0; ks < 4; ks++) {
            const int kc = ks * 8;
            uint32_t a[2][4], bfr[8][2];
#pragma unroll
            for (int i = 0; i < 2; i++) {
                const int r = 32 * wq + 16 * i + g;
                a[i][0] = uf(as[r * SA + kc + tig]);
                a[i][1] = uf(as[(r + 8) * SA + kc + tig]);
                a[i][2] = uf(as[r * SA + kc + tig + 4]);
                a[i][3] = uf(as[(r + 8) * SA + kc + tig + 4]);
            }
#pragma unroll
            for (int j = 0; j < 8; j++) {
                const int n0 = 64 * wn + 8 * j + g;
                bfr[j][0] = uf(ws[n0 * SA + kc + tig]);
                bfr[j][1] = uf(ws[n0 * SA + kc + tig + 4]);
            }
#pragma unroll
            for (int i = 0; i < 2; i++)
#pragma unroll
                for (int j = 0; j < 8; j++) mma8(acc[i][j], a[i], bfr[j]);
        }
    }
#pragma unroll
    for (int i = 0; i < 2; i++) {
        const int r0 = bm + 32 * wq + 16 * i + g;
#pragma unroll
        for (int j = 0; j < 8; j++) {
            const int cg = bn + 64 * wn + 8 * j + 2 * tig;
            float2 bb = *(const float2*)&bias[cg];
            float2 o0 = make_float2(acc[i][j].x + bb.x, acc[i][j].y + bb.y);
            float2 o1 = make_float2(acc[i][j].z + bb.x, acc[i][j].w + bb.y);
            if (resid) {
                float2 ra = *(const float2*)&resid[(size_t)r0 * GN + cg];
                float2 rb = *(const float2*)&resid[(size_t)(r0 + 8) * GN + cg];
                o0.x += ra.x; o0.y += ra.y; o1.x += rb.x; o1.y += rb.y;
            }
            if (round_out) {
                o0.x = tf32r(o0.x); o0.y = tf32r(o0.y);
                o1.x = tf32r(o1.x); o1.y = tf32r(o1.y);
            }
            *(float2*)&C[(size_t)r0 * GN + cg] = o0;
            *(float2*)&C[(size_t)(r0 + 8) * GN + cg] = o1;
        }
    }
}

// ---------------- single-pass TC attention, cp.async double-buffered ---------
// qtile=128, ktile=64. Q frags in regs. Writes UNNORMALIZED exp to attn,
// rowsum inv to g_inv, tf32-rounded normalized ctx to g_ctx.
#define AST 68   // Q/K/P stride (272B, 16B-aligned)
#define VST 72   // V stride (288B)
#define OFF_KS  8704                       // Ps = 128*AST = 8704 floats
#define OFF_VS  (OFF_KS + 2 * 64 * AST)    // 8704 + 8704 = 17408
#define OFF_RED (OFF_VS + 2 * 64 * VST)    // 17408 + 9216 = 26624
#define OFF_INV (OFF_RED + 128 * 8)        // 27648
#define OFF_MS  (OFF_INV + 128)            // 27776 floats; then 2*8192 mask bytes
#define ATTN_SMEM_BYTES (OFF_MS * 4 + 2 * 8192)   // 127488
__global__ __launch_bounds__(256) void attn_tc(float* __restrict__ attn_out)
{
    extern __shared__ float sm[];
    float* Ps   = sm;
    float* Ksb  = sm + OFF_KS;
    float* Vsb  = sm + OFF_VS;
    float* red  = sm + OFF_RED;
    float* invs = sm + OFF_INV;
    char*  Msb  = (char*)(sm + OFF_MS);

    const int t = threadIdx.x;
    const int lane = t & 31, w = t >> 5;
    const int g = lane >> 2, tig = lane & 3;
    const int wq = w >> 1, wn = w & 1;
    const int qt = blockIdx.x, h = blockIdx.y, b = blockIdx.z;
    const int qg0 = qt * 128;
    const size_t qrowg = (size_t)(b * S_) + qg0;
    const int lr = t >> 1, half = t & 1;          // 128-row ops
    const int kr = t >> 2, kq = t & 3;            // 64-row ops

    const float* Kb = g_K + (size_t)(b * S_) * D_ + h * DK_;
    const float* Vb = g_V + (size_t)(b * S_) * D_ + h * DK_;
    const unsigned char* Mb = g_mask + (size_t)(b * S_ + qg0) * S_;
    const size_t attn_row0 = (size_t)(h * B_ + b) * S_ + qg0;

    // stage Q (pre-rounded) into Ps, lift fragments with exact *0.125 scale
    {
        const float* Qg = g_Q + (qrowg + lr) * D_ + h * DK_ + half * 32;
        float* dst = &Ps[lr * AST + half * 32];
#pragma unroll
        for (int jj = 0; jj < 8; jj++)
            *(float4*)(dst + 4 * jj) = *(const float4*)(Qg + 4 * jj);
    }
    __syncthreads();
    uint32_t qa[2][8][4];
#pragma unroll
    for (int i = 0; i < 2; i++) {
        const int r = 32 * wq + 16 * i + g;
#pragma unroll
        for (int ks = 0; ks < 8; ks++) {
            const int kd = ks * 8;
            qa[i][ks][0] = uf(SCALE_ * Ps[r * AST + kd + tig]);
            qa[i][ks][1] = uf(SCALE_ * Ps[(r + 8) * AST + kd + tig]);
            qa[i][ks][2] = uf(SCALE_ * Ps[r * AST + kd + tig + 4]);
            qa[i][ks][3] = uf(SCALE_ * Ps[(r + 8) * AST + kd + tig + 4]);
        }
    }

    // preload stage 0 (kc = 0)
    {
        float* dk = Ksb + kr * AST + kq * 16;
        float* dv = Vsb + kr * VST + kq * 16;
        const float* Kg = Kb + (size_t)kr * D_ + kq * 16;
        const float* Vg = Vb + (size_t)kr * D_ + kq * 16;
#pragma unroll
        for (int p = 0; p < 4; p++) { cpa16(dk + 4 * p, Kg + 4 * p); cpa16(dv + 4 * p, Vg + 4 * p); }
        char* dm = Msb + lr * 64 + half * 32;
        const unsigned char* mg = Mb + (size_t)lr * S_ + half * 32;
        cpa16(dm, mg); cpa16(dm + 16, mg + 16);
        cpa_commit();
    }

    float rs[2][2] = {{0.f, 0.f}, {0.f, 0.f}};
    float4 o[2][4];
#pragma unroll
    for (int i = 0; i < 2; i++)
#pragma unroll
        for (int j = 0; j < 4; j++) o[i][j] = make_float4(0.f, 0.f, 0.f, 0.f);

    for (int ic = 0; ic < S_ / 64; ic++) {
        const int kc = ic * 64;
        cpa_wait0();
        __syncthreads();
        if (ic + 1 < S_ / 64) {
            const int st = (ic + 1) & 1;
            float* dk = Ksb + st * (64 * AST) + kr * AST + kq * 16;
            float* dv = Vsb + st * (64 * VST) + kr * VST + kq * 16;
            const float* Kg = Kb + (size_t)(kc + 64 + kr) * D_ + kq * 16;
            const float* Vg = Vb + (size_t)(kc + 64 + kr) * D_ + kq * 16;
#pragma unroll
            for (int p = 0; p < 4; p++) { cpa16(dk + 4 * p, Kg + 4 * p); cpa16(dv + 4 * p, Vg + 4 * p); }
            char* dm = Msb + st * 8192 + lr * 64 + half * 32;
            const unsigned char* mg = Mb + (size_t)lr * S_ + kc + 64 + half * 32;
            cpa16(dm, mg); cpa16(dm + 16, mg + 16);
            cpa_commit();
        }
        const float* Ks = Ksb + (ic & 1) * (64 * AST);
        const float* Vs = Vsb + (ic & 1) * (64 * VST);
        const char*  Ms = Msb + (ic & 1) * 8192;

        // ---- QK
        float4 s[2][4];
#pragma unroll
        for (int i = 0; i < 2; i++)
#pragma unroll
            for (int j = 0; j < 4; j++) s[i][j] = make_float4(0.f, 0.f, 0.f, 0.f);
#pragma unroll
        for (int ks = 0; ks < 8; ks++) {
            const int kd = ks * 8;
            uint32_t bf[4][2];
#pragma unroll
            for (int j = 0; j < 4; j++) {
                const int n0 = 32 * wn + 8 * j + g;
                bf[j][0] = uf(Ks[n0 * AST + kd + tig]);
                bf[j][1] = uf(Ks[n0 * AST + kd + tig + 4]);
            }
#pragma unroll
            for (int i = 0; i < 2; i++)
#pragma unroll
                for (int j = 0; j < 4; j++) mma8(s[i][j], qa[i][ks], bf[j]);
        }

        // ---- exp + mask + rowsum; raw p -> gmem attn; tf32r(p) -> Ps
#pragma unroll
        for (int i = 0; i < 2; i++) {
            const int r = 32 * wq + 16 * i + g;
#pragma unroll
            for (int j = 0; j < 4; j++) {
                const int c0 = 32 * wn + 8 * j + 2 * tig;
                float p0 = Ms[r * 64 + c0]           ? 0.f : __expf(s[i][j].x);
                float p1 = Ms[r * 64 + c0 + 1]       ? 0.f : __expf(s[i][j].y);
                float p2 = Ms[(r + 8) * 64 + c0]     ? 0.f : __expf(s[i][j].z);
                float p3 = Ms[(r + 8) * 64 + c0 + 1] ? 0.f : __expf(s[i][j].w);
                rs[i][0] += p0 + p1; rs[i][1] += p2 + p3;
                *(float2*)(attn_out + (attn_row0 + r) * S_ + kc + c0)     = make_float2(p0, p1);
                *(float2*)(attn_out + (attn_row0 + r + 8) * S_ + kc + c0) = make_float2(p2, p3);
                Ps[r * AST + c0]           = tf32r(p0);
                Ps[r * AST + c0 + 1]       = tf32r(p1);
                Ps[(r + 8) * AST + c0]     = tf32r(p2);
                Ps[(r + 8) * AST + c0 + 1] = tf32r(p3);
            }
        }
        __syncthreads();

        // ---- PV (unnormalized accumulate)
#pragma unroll
        for (int ks = 0; ks < 8; ks++) {
            const int kd = ks * 8;
            uint32_t pa[2][4], vb[4][2];
#pragma unroll
            for (int i = 0; i < 2; i++) {
                const int r = 32 * wq + 16 * i + g;
                pa[i][0] = uf(Ps[r * AST + kd + tig]);
                pa[i][1] = uf(Ps[(r + 8) * AST + kd + tig]);
                pa[i][2] = uf(Ps[r * AST + kd + tig + 4]);
                pa[i][3] = uf(Ps[(r + 8) * AST + kd + tig + 4]);
            }
#pragma unroll
            for (int j = 0; j < 4; j++) {
                const int d0 = 32 * wn + 8 * j + g;
                vb[j][0] = uf(Vs[(kd + tig) * VST + d0]);
                vb[j][1] = uf(Vs[(kd + tig + 4) * VST + d0]);
            }
#pragma unroll
            for (int i = 0; i < 2; i++)
#pragma unroll
                for (int j = 0; j < 4; j++) mma8(o[i][j], pa[i], vb[j]);
        }
    }

    // ---- rowsum reduction -> inv, g_inv
    __syncthreads();
#pragma unroll
    for (int i = 0; i < 2; i++) {
        const int r = 32 * wq + 16 * i + g;
        red[r * 8 + wn * 4 + tig]       = rs[i][0];
        red[(r + 8) * 8 + wn * 4 + tig] = rs[i][1];
    }
    __syncthreads();
    if (t < 128) {
        float ssum = 0.f;
#pragma unroll
        for (int j = 0; j < 8; j++) ssum += red[t * 8 + j];
        const float iv = 1.0f / ssum;
        invs[t] = iv;
        g_inv[attn_row0 + t] = iv;
    }
    __syncthreads();

    // ---- ctx epilogue: normalized + tf32-rounded, staged for coalesced store
#pragma unroll
    for (int i = 0; i < 2; i++) {
        const int r = 32 * wq + 16 * i + g;
        const float iv0 = invs[r], iv1 = invs[r + 8];
#pragma unroll
        for (int j = 0; j < 4; j++) {
            const int c0 = 32 * wn + 8 * j + 2 * tig;
            Ps[r * AST + c0]           = tf32r(o[i][j].x * iv0);
            Ps[r * AST + c0 + 1]       = tf32r(o[i][j].y * iv0);
            Ps[(r + 8) * AST + c0]     = tf32r(o[i][j].z * iv1);
            Ps[(r + 8) * AST + c0 + 1] = tf32r(o[i][j].w * iv1);
        }
    }
    __syncthreads();
    {
        float* cg = g_ctx + (qrowg + lr) * D_ + h * DK_ + half * 32;
        const float* src = &Ps[lr * AST + half * 32];
#pragma unroll
        for (int jj = 0; jj < 8; jj++)
            *(float4*)(cg + 4 * jj) = *(const float4*)(src + 4 * jj);
    }
}

// ---------------- attn normalization: attn *= 1/rowsum -----------------------
__global__ __launch_bounds__(256) void norm_attn_kernel(float* __restrict__ attn)
{
    const size_t n4 = NATTN / 4;
    const size_t stride = (size_t)gridDim.x * blockDim.x;
    float4* p = (float4*)attn;
    for (size_t i = (size_t)blockIdx.x * blockDim.x + threadIdx.x; i < n4; i += stride) {
        const size_t row = i >> 9;           // (i*4)/2048
        const float inv = g_inv[row];
        float4 v = p[i];
        v.x *= inv; v.y *= inv; v.z *= inv; v.w *= inv;
        p[i] = v;
    }
}

// ---------------- layernorm --------------------------------------------------
__global__ __launch_bounds__(256) void ln_kernel(
    const float* __restrict__ X, const float* __restrict__ gamma,
    const float* __restrict__ beta, float* __restrict__ out)
{
    const int r = blockIdx.x;
    const int t = threadIdx.x;
    float4 v = *(const float4*)&X[(size_t)r * D_ + t * 4];
    float s  = v.x + v.y + v.z + v.w;
    float sq = v.x * v.x + v.y * v.y + v.z * v.z + v.w * v.w;
#pragma unroll
    for (int o = 16; o > 0; o >>= 1) {
        s  += __shfl_xor_sync(0xFFFFFFFFu, s, o);
        sq += __shfl_xor_sync(0xFFFFFFFFu, sq, o);
    }
    __shared__ float ws[8], wqv[8];
    const int w = t >> 5;
    if ((t & 31) == 0) { ws[w] = s; wqv[w] = sq; }
    __syncthreads();
    if (t < 32) {
        float a  = (t < 8) ? ws[t] : 0.0f;
        float b2 = (t < 8) ? wqv[t] : 0.0f;
#pragma unroll
        for (int o = 4; o > 0; o >>= 1) {
            a  += __shfl_xor_sync(0xFFFFFFFFu, a, o);
            b2 += __shfl_xor_sync(0xFFFFFFFFu, b2, o);
        }
        if (t == 0) { ws[0] = a; wqv[0] = b2; }
    }
    __syncthreads();
    const float mean = ws[0] * (1.0f / D_);
    const float var  = wqv[0] * (1.0f / D_) - mean * mean;
    const float rstd = rsqrtf(var + LN_EPS_);
    float4 gm = *(const float4*)&gamma[t * 4];
    float4 be = *(const float4*)&beta[t * 4];
    float4 o4;
    o4.x = gm.x * (v.x - mean) * rstd + be.x;
    o4.y = gm.y * (v.y - mean) * rstd + be.y;
    o4.z = gm.z * (v.z - mean) * rstd + be.z;
    o4.w = gm.w * (v.w - mean) * rstd + be.w;
    *(float4*)&out[(size_t)r * D_ + t * 4] = o4;
}

// ---------------- launch -----------------------------------------------------
extern "C" void kernel_launch(void* const* d_in, const int* in_sizes, int n_in,
                              void* d_out, int out_size)
{
    (void)in_sizes; (void)n_in; (void)out_size;
    const float* query = (const float*)d_in[0];
    const float* key   = (const float*)d_in[1];
    const float* value = (const float*)d_in[2];
    const void*  mask  = d_in[3];
    const float* Wq = (const float*)d_in[4];
    const float* bq = (const float*)d_in[5];
    const float* Wk = (const float*)d_in[6];
    const float* bk = (const float*)d_in[7];
    const float* Wv = (const float*)d_in[8];
    const float* bv = (const float*)d_in[9];
    const float* Wo = (const float*)d_in[10];
    const float* bo = (const float*)d_in[11];
    const float* gamma = (const float*)d_in[12];
    const float* beta  = (const float*)d_in[13];

    float* out  = (float*)d_out;
    float* attn = out + BSD;

    float* gQ;   cudaGetSymbolAddress((void**)&gQ,   g_Q);
    float* gK;   cudaGetSymbolAddress((void**)&gK,   g_K);
    float* gV;   cudaGetSymbolAddress((void**)&gV,   g_V);
    float* gCtx; cudaGetSymbolAddress((void**)&gCtx, g_ctx);
    float* gOut; cudaGetSymbolAddress((void**)&gOut, g_out);
    float* gWr;  cudaGetSymbolAddress((void**)&gWr,  g_Wr);

    cudaFuncSetAttribute(gemm_tc, cudaFuncAttributeMaxDynamicSharedMemorySize, GEMM_SMEM_BYTES);
    cudaFuncSetAttribute(attn_tc, cudaFuncAttributeMaxDynamicSharedMemorySize, ATTN_SMEM_BYTES);

    detect_mask_kernel<<<1, 256>>>((const unsigned int*)mask);
    convert_mask_kernel<<<4096, 256>>>(mask);

    const size_t nW4 = (size_t)D_ * D_ / 4;   // 262144
    const size_t nX4 = BSD / 4;               // 2097152
    dim3 gg(GN / 128, GM / 128);

    // Q = round(query) @ round(Wq)^T + bq   (output tf32-rounded)
    round_copy<<<1024, 256>>>(Wq, gWr, nW4);
    round_copy<<<2048, 256>>>(query, gCtx, nX4);
    gemm_tc<<<gg, 256, GEMM_SMEM_BYTES>>>(gCtx, gWr, bq, nullptr, gQ, 1);
    // K
    round_copy<<<1024, 256>>>(Wk, gWr, nW4);
    round_copy<<<2048, 256>>>(key, gCtx, nX4);
    gemm_tc<<<gg, 256, GEMM_SMEM_BYTES>>>(gCtx, gWr, bk, nullptr, gK, 1);
    // V
    round_copy<<<1024, 256>>>(Wv, gWr, nW4);
    round_copy<<<2048, 256>>>(value, gCtx, nX4);
    gemm_tc<<<gg, 256, GEMM_SMEM_BYTES>>>(gCtx, gWr, bv, nullptr, gV, 1);

    attn_tc<<<dim3(S_ / 128, H_, B_), 256, ATTN_SMEM_BYTES>>>(attn);

    // out-proj: ctx (already tf32) @ round(Wo)^T + bo + query
    round_copy<<<1024, 256>>>(Wo, gWr, nW4);
    gemm_tc<<<gg, 256, GEMM_SMEM_BYTES>>>(gCtx, gWr, bo, query, gOut, 0);

    norm_attn_kernel<<<8192, 256>>>(attn);
    ln_kernel<<<B_ * S_, 256>>>(gOut, gamma, beta, out);
}